// round 16
// baseline (speedup 1.0000x reference)
#include <cuda_runtime.h>
#include <cuda_fp16.h>
#include <math.h>

#define Nn    50000
#define NPAD  50048            // 782 * 64
#define Ee    1600000
#define F     128
#define ALPHA 0.2f

typedef unsigned long long ull;

// ---------------- scratch (static device globals; no allocation) -------------
__device__ __half d_hwh[NPAD * F];    // fp16 hw = h @ W
__device__ float  d_wa_src[F];        // W @ a_src
__device__ float  d_wa_dst[F];        // W @ a_dst
__device__ float  d_ssrc[Nn];
__device__ float  d_sdst[Nn];
__device__ int    d_rowptr[Nn + 1];

// ---------------- PTX helpers ------------------------------------------------
__device__ __forceinline__ unsigned s2u(const void* p) {
    return (unsigned)__cvta_generic_to_shared(p);
}
__device__ __forceinline__ void ldsm_x4(unsigned& r0, unsigned& r1,
                                        unsigned& r2, unsigned& r3, unsigned a) {
    asm volatile("ldmatrix.sync.aligned.m8n8.x4.shared.b16 {%0,%1,%2,%3}, [%4];"
                 : "=r"(r0), "=r"(r1), "=r"(r2), "=r"(r3) : "r"(a));
}
__device__ __forceinline__ void ldsm_x4_t(unsigned& r0, unsigned& r1,
                                          unsigned& r2, unsigned& r3, unsigned a) {
    asm volatile("ldmatrix.sync.aligned.m8n8.x4.trans.shared.b16 {%0,%1,%2,%3}, [%4];"
                 : "=r"(r0), "=r"(r1), "=r"(r2), "=r"(r3) : "r"(a));
}
__device__ __forceinline__ void mma16816(float* c, const unsigned* a,
                                         unsigned b0, unsigned b1) {
    asm volatile(
        "mma.sync.aligned.m16n8k16.row.col.f32.f16.f16.f32 "
        "{%0,%1,%2,%3},{%4,%5,%6,%7},{%8,%9},{%0,%1,%2,%3};"
        : "+f"(c[0]), "+f"(c[1]), "+f"(c[2]), "+f"(c[3])
        : "r"(a[0]), "r"(a[1]), "r"(a[2]), "r"(a[3]), "r"(b0), "r"(b1));
}
__device__ __forceinline__ ull pack2(float x, float y) {
    ull r;
    asm("mov.b64 %0, {%1, %2};" : "=l"(r) : "f"(x), "f"(y));
    return r;
}
__device__ __forceinline__ void unpack2(ull v, float& x, float& y) {
    asm("mov.b64 {%0, %1}, %2;" : "=f"(x), "=f"(y) : "l"(v));
}
__device__ __forceinline__ ull add2(ull a, ull b) {
    ull r;
    asm("add.rn.f32x2 %0, %1, %2;" : "=l"(r) : "l"(a), "l"(b));
    return r;
}
__device__ __forceinline__ ull mul2(ull a, ull b) {
    ull r;
    asm("mul.rn.f32x2 %0, %1, %2;" : "=l"(r) : "l"(a), "l"(b));
    return r;
}

// =============================================================================
// K0: tiny prep — wa_src/wa_dst = W @ a  (one block, 2 threads per W row)
// =============================================================================
__global__ void prep_kernel(const float* __restrict__ W,
                            const float* __restrict__ a_src,
                            const float* __restrict__ a_dst) {
    const int t  = threadIdx.x;       // 256 threads
    const int r  = t >> 1;            // 0..127
    const int hh = t & 1;
    const float4* __restrict__ W4  = reinterpret_cast<const float4*>(W);
    const float4* __restrict__ as4 = reinterpret_cast<const float4*>(a_src);
    const float4* __restrict__ ad4 = reinterpret_cast<const float4*>(a_dst);
    float ps = 0.f, pd = 0.f;
    #pragma unroll
    for (int j = 0; j < 16; ++j) {
        float4 wv = __ldg(&W4[r * 32 + hh * 16 + j]);
        float4 av = __ldg(&as4[hh * 16 + j]);
        float4 dv = __ldg(&ad4[hh * 16 + j]);
        ps += wv.x * av.x + wv.y * av.y + wv.z * av.z + wv.w * av.w;
        pd += wv.x * dv.x + wv.y * dv.y + wv.z * dv.z + wv.w * dv.w;
    }
    ps += __shfl_xor_sync(0xffffffffu, ps, 1);
    pd += __shfl_xor_sync(0xffffffffu, pd, 1);
    if (hh == 0) { d_wa_src[r] = ps; d_wa_dst[r] = pd; }
}

// =============================================================================
// K1: hw = fp16(h) @ fp16(W) (mma.sync) + exact fp32 scores vs d_wa_*
// A staged from fp32 h with inline cvt; B staged from fp32 W with inline cvt.
// Static smem = 16KB + 32KB = exactly 48KB.
// =============================================================================
__global__ __launch_bounds__(256) void hgemm_kernel(const float* __restrict__ h,
                                                    const float* __restrict__ W) {
    __shared__ __align__(16) __half As[64 * F];    // 16 KB
    __shared__ __align__(16) __half Bs[F * F];     // 32 KB

    const int t       = threadIdx.x;
    const int rowBase = blockIdx.x * 64;
    const int lane    = t & 31;
    const int wid     = t >> 5;
    const int wm      = wid >> 2;
    const int wn      = wid & 3;
    const float4* __restrict__ W4 = reinterpret_cast<const float4*>(W);

    // ---- stage A from fp32 h + exact score partials --------------------------
    {
        const int r   = t >> 2;
        const int seg = t & 3;
        const int gr  = rowBase + r;
        const bool ok = gr < Nn;
        const float4* __restrict__ h4  = reinterpret_cast<const float4*>(h);
        const float4* __restrict__ ws4 = reinterpret_cast<const float4*>(d_wa_src);
        const float4* __restrict__ wd4 = reinterpret_cast<const float4*>(d_wa_dst);
        uint4* __restrict__ As4 = reinterpret_cast<uint4*>(As);

        float ps = 0.f, pd = 0.f;
        #pragma unroll
        for (int j = 0; j < 8; j += 2) {
            float4 v0 = ok ? __ldg(&h4[gr * 32 + seg * 8 + j])     : make_float4(0,0,0,0);
            float4 v1 = ok ? __ldg(&h4[gr * 32 + seg * 8 + j + 1]) : make_float4(0,0,0,0);
            float4 s0 = __ldg(&ws4[seg * 8 + j]),  s1 = __ldg(&ws4[seg * 8 + j + 1]);
            float4 q0 = __ldg(&wd4[seg * 8 + j]),  q1 = __ldg(&wd4[seg * 8 + j + 1]);
            ps += v0.x*s0.x + v0.y*s0.y + v0.z*s0.z + v0.w*s0.w
                + v1.x*s1.x + v1.y*s1.y + v1.z*s1.z + v1.w*s1.w;
            pd += v0.x*q0.x + v0.y*q0.y + v0.z*q0.z + v0.w*q0.w
                + v1.x*q1.x + v1.y*q1.y + v1.z*q1.z + v1.w*q1.w;
            __half2 p0 = __float22half2_rn(make_float2(v0.x, v0.y));
            __half2 p1 = __float22half2_rn(make_float2(v0.z, v0.w));
            __half2 p2 = __float22half2_rn(make_float2(v1.x, v1.y));
            __half2 p3 = __float22half2_rn(make_float2(v1.z, v1.w));
            uint4 u;
            u.x = *reinterpret_cast<unsigned*>(&p0);
            u.y = *reinterpret_cast<unsigned*>(&p1);
            u.z = *reinterpret_cast<unsigned*>(&p2);
            u.w = *reinterpret_cast<unsigned*>(&p3);
            int g = seg * 4 + (j >> 1);
            As4[r * 16 + (g ^ (r & 7))] = u;
        }
        ps += __shfl_xor_sync(0xffffffffu, ps, 1);
        ps += __shfl_xor_sync(0xffffffffu, ps, 2);
        pd += __shfl_xor_sync(0xffffffffu, pd, 1);
        pd += __shfl_xor_sync(0xffffffffu, pd, 2);
        if (seg == 0 && ok) { d_ssrc[gr] = ps; d_sdst[gr] = pd; }
    }
    // ---- stage B from fp32 W with inline conversion --------------------------
    {
        uint4* __restrict__ Bs4 = reinterpret_cast<uint4*>(Bs);
        #pragma unroll
        for (int i = 0; i < 8; ++i) {
            int G = i * 256 + t;            // fp16 granule 0..2047
            int r = G >> 4, g = G & 15;
            float4 f0 = __ldg(&W4[r * 32 + g * 2]);
            float4 f1 = __ldg(&W4[r * 32 + g * 2 + 1]);
            __half2 p0 = __float22half2_rn(make_float2(f0.x, f0.y));
            __half2 p1 = __float22half2_rn(make_float2(f0.z, f0.w));
            __half2 p2 = __float22half2_rn(make_float2(f1.x, f1.y));
            __half2 p3 = __float22half2_rn(make_float2(f1.z, f1.w));
            uint4 u;
            u.x = *reinterpret_cast<unsigned*>(&p0);
            u.y = *reinterpret_cast<unsigned*>(&p1);
            u.z = *reinterpret_cast<unsigned*>(&p2);
            u.w = *reinterpret_cast<unsigned*>(&p3);
            Bs4[r * 16 + (g ^ (r & 7))] = u;
        }
    }
    __syncthreads();

    const unsigned Ab = s2u(As), Bb = s2u(Bs);
    float c[2][4][4];
    #pragma unroll
    for (int i = 0; i < 2; ++i)
        #pragma unroll
        for (int j = 0; j < 4; ++j)
            #pragma unroll
            for (int q = 0; q < 4; ++q) c[i][j][q] = 0.f;

    #pragma unroll
    for (int kk = 0; kk < 8; ++kk) {
        unsigned a[2][4], b[2][4];
        #pragma unroll
        for (int i = 0; i < 2; ++i) {
            int r = wm * 32 + i * 16 + (lane & 15);
            int g = kk * 2 + (lane >> 4);
            ldsm_x4(a[i][0], a[i][1], a[i][2], a[i][3],
                    Ab + (r * 16 + (g ^ (r & 7))) * 16);
        }
        #pragma unroll
        for (int jp = 0; jp < 2; ++jp) {
            int kr = kk * 16 + (lane & 15);
            int g  = wn * 4 + jp * 2 + (lane >> 4);
            ldsm_x4_t(b[jp][0], b[jp][1], b[jp][2], b[jp][3],
                      Bb + (kr * 16 + (g ^ (kr & 7))) * 16);
        }
        #pragma unroll
        for (int i = 0; i < 2; ++i)
            #pragma unroll
            for (int j = 0; j < 4; ++j)
                mma16816(c[i][j], a[i], b[j >> 1][(j & 1) * 2],
                         b[j >> 1][(j & 1) * 2 + 1]);
    }

    const int g  = lane >> 2;
    const int cp = (lane & 3) * 2;
    #pragma unroll
    for (int i = 0; i < 2; ++i)
        #pragma unroll
        for (int j = 0; j < 4; ++j) {
            int gr = rowBase + wm * 32 + i * 16 + g;
            int gc = wn * 32 + j * 8 + cp;
            __half2 lo = __float22half2_rn(make_float2(c[i][j][0], c[i][j][1]));
            __half2 hi = __float22half2_rn(make_float2(c[i][j][2], c[i][j][3]));
            *reinterpret_cast<__half2*>(&d_hwh[gr * F + gc])       = lo;
            *reinterpret_cast<__half2*>(&d_hwh[(gr + 8) * F + gc]) = hi;
        }
}

// =============================================================================
// K2: edge-parallel rowptr from sorted row
// =============================================================================
__global__ void rowptr_kernel(const int* __restrict__ row) {
    int i = blockIdx.x * blockDim.x + threadIdx.x;
    if (i >= Ee) return;
    int a = __ldg(&row[i]);
    int b = (i + 1 < Ee) ? __ldg(&row[i + 1]) : Nn;
    for (int r = a + 1; r <= b; ++r) d_rowptr[r] = i + 1;
    if (i == 0)
        for (int r = 0; r <= a; ++r) d_rowptr[r] = 0;
}

// =============================================================================
// K3: warp-per-node: online softmax + BRANCHLESS padded fp16-accumulate gather.
// Partial batches pad with (cl=0, wq=0): loads hit the L1-hot row 0 and HFMA2
// adds zero.  The 16-iteration gather is fully unrolled with static flushes.
// =============================================================================
__global__ __launch_bounds__(256) void edge_kernel(const int* __restrict__ col,
                                                   float* __restrict__ out) {
    const int gw   = (blockIdx.x * blockDim.x + threadIdx.x) >> 5;
    const int lane = threadIdx.x & 31;
    if (gw >= Nn) return;
    const int   eb   = d_rowptr[gw];
    const int   ee   = d_rowptr[gw + 1];
    const float ssrc = d_ssrc[gw];

    const uint4* __restrict__ hw4 = reinterpret_cast<const uint4*>(d_hwh);
    const int half_id = lane >> 4;
    const int fg      = lane & 15;

    float m = -1e30f, sum = 0.f;
    ull facc[4] = {0ull, 0ull, 0ull, 0ull};
    const __half2 hz = __float2half2_rn(0.f);

    for (int e0 = eb; e0 < ee; e0 += 32) {
        const int e = e0 + lane;

        // ---- per-lane score + online softmax state ---------------------------
        float v = -1e30f; int cl = 0;
        if (e < ee) {
            cl = __ldg(&col[e]);
            float s = ssrc + __ldg(&d_sdst[cl]);
            v = (s > 0.f) ? s : ALPHA * s;
        }
        float bm = v;
        #pragma unroll
        for (int off = 16; off; off >>= 1)
            bm = fmaxf(bm, __shfl_xor_sync(0xffffffffu, bm, off));
        if (bm > m) {
            const float sc = __expf(m - bm);
            sum *= sc;
            const ull sc2 = pack2(sc, sc);
            facc[0] = mul2(facc[0], sc2);
            facc[1] = mul2(facc[1], sc2);
            facc[2] = mul2(facc[2], sc2);
            facc[3] = mul2(facc[3], sc2);
            m = bm;
        }
        const __half   wh = __float2half_rn(__expf(v - m));   // 0 for padded lanes
        const unsigned wq = (unsigned)__half_as_ushort(wh);
        float bs = __half2float(wh);
        #pragma unroll
        for (int off = 16; off; off >>= 1)
            bs += __shfl_xor_sync(0xffffffffu, bs, off);
        sum += bs;

        // ---- branchless padded gather (16 static iterations) -----------------
        const unsigned pk = (wq << 16) | (unsigned)cl;        // col < 65536
        __half2 hacc0 = hz, hacc1 = hz, hacc2 = hz, hacc3 = hz;

        #pragma unroll
        for (int j = 0; j < 32; j += 2) {
            const unsigned p  = __shfl_sync(0xffffffffu, pk, j + half_id);
            const __half2  w2 = __half2half2(__ushort_as_half((unsigned short)(p >> 16)));
            const uint4    q  = __ldg(&hw4[(p & 0xffffu) * 16 + fg]);
            hacc0 = __hfma2(*reinterpret_cast<const __half2*>(&q.x), w2, hacc0);
            hacc1 = __hfma2(*reinterpret_cast<const __half2*>(&q.y), w2, hacc1);
            hacc2 = __hfma2(*reinterpret_cast<const __half2*>(&q.z), w2, hacc2);
            hacc3 = __hfma2(*reinterpret_cast<const __half2*>(&q.w), w2, hacc3);
            if (j == 6 || j == 14 || j == 22 || j == 30) {    // static 8-edge flush
                float2 f0 = __half22float2(hacc0);
                float2 f1 = __half22float2(hacc1);
                float2 f2 = __half22float2(hacc2);
                float2 f3 = __half22float2(hacc3);
                facc[0] = add2(facc[0], pack2(f0.x, f0.y));
                facc[1] = add2(facc[1], pack2(f1.x, f1.y));
                facc[2] = add2(facc[2], pack2(f2.x, f2.y));
                facc[3] = add2(facc[3], pack2(f3.x, f3.y));
                hacc0 = hz; hacc1 = hz; hacc2 = hz; hacc3 = hz;
            }
        }
    }

    // ---- merge half-warps, normalize, elu, store -----------------------------
    float a[8];
    unpack2(facc[0], a[0], a[1]);
    unpack2(facc[1], a[2], a[3]);
    unpack2(facc[2], a[4], a[5]);
    unpack2(facc[3], a[6], a[7]);
    #pragma unroll
    for (int f = 0; f < 8; ++f)
        a[f] += __shfl_xor_sync(0xffffffffu, a[f], 16);

    if (lane < 16) {
        const float inv = (ee > eb) ? (1.f / sum) : 0.f;
        float o[8];
        #pragma unroll
        for (int f = 0; f < 8; ++f) {
            float x = a[f] * inv;
            o[f] = (x > 0.f) ? x : expm1f(x);
        }
        float4* op = reinterpret_cast<float4*>(&out[gw * F + fg * 8]);
        op[0] = make_float4(o[0], o[1], o[2], o[3]);
        op[1] = make_float4(o[4], o[5], o[6], o[7]);
    }
}

// =============================================================================
extern "C" void kernel_launch(void* const* d_in, const int* in_sizes, int n_in,
                              void* d_out, int out_size) {
    const float* h     = (const float*)d_in[0];
    const float* W     = (const float*)d_in[1];
    const float* a_src = (const float*)d_in[2];
    const float* a_dst = (const float*)d_in[3];
    const int*   row   = (const int*)d_in[4];
    const int*   col   = (const int*)d_in[5];
    float*       out   = (float*)d_out;

    prep_kernel<<<1, 256>>>(W, a_src, a_dst);
    hgemm_kernel<<<NPAD / 64, 256>>>(h, W);
    rowptr_kernel<<<(Ee + 255) / 256, 256>>>(row);
    edge_kernel<<<(Nn * 32 + 255) / 256, 256>>>(col, out);
}